// round 16
// baseline (speedup 1.0000x reference)
#include <cuda_runtime.h>
#include <cuda_fp16.h>
#include <cstdint>

// ---------------------------------------------------------------------------
// LoRA multi-task MLP via mma.sync fp16 (plain sm_100 target).
// Round 16: persistent-grid GEMM (296 CTAs, 2/SM). Stage ring runs a global
// (tile,chunk) prefetch sequence 2 ahead of compute, so epilogues and tile
// switches never drain the pipeline and wave tails vanish. Epilogue smem is
// a dedicated region beyond the stages; per-warp P' partials go straight to
// 64 global slabs (deterministic unique-writer), summed by reduceP.
// Mainloop math identical to the R14 champion (1-term fp16, BM=BN=128,
// BK=64, 3 stages, 8 warps, 64x32 warp tile).
// ---------------------------------------------------------------------------

#define T_TASKS 8
#define RNK 8
#define M_ROWS 8192

#define BM 128
#define BN 128
#define BK 64                          // K elements per chunk (128 B fp16 rows)
#define STAGES 3
#define TILE_BYTES (128 * 128)         // 16 KB per operand tile
#define STAGE_BYTES (2 * TILE_BYTES)   // A | W = 32 KB
#define EPI_OFF (STAGES * STAGE_BYTES) // 96 KB
#define SMEM_BYTES (EPI_OFF + 13312)   // + epilogue region = 111616 (2 CTAs/SM)
#define GRID_P 296                     // persistent grid: 2 x 148 SMs

// ---- scratch (device globals; no allocation allowed) ----------------------
__device__ __half g_A0[(size_t)M_ROWS * 2048];   // fp16 activations, 32 MB
__device__ __half g_A1[(size_t)M_ROWS * 2048];   // fp16 activations, 32 MB
__device__ __half g_B [(size_t)8 * 1024 * 1024]; // W^T fp16 slabs, 16 MB
__device__ float g_p [M_ROWS * RNK];
__device__ float g_pp[64 * M_ROWS * RNK];        // per-(nblk, warpgrp) slabs, 16 MB

// W slab offsets (halves)
#define W0_OFF 0u
#define W1_OFF (2u * 1024 * 1024)
#define W2_OFF (6u * 1024 * 1024)

// ---------------------------------------------------------------------------
__device__ __forceinline__ uint32_t smem_u32(const void* p) {
    uint32_t a;
    asm("{ .reg .u64 t; cvta.to.shared.u64 t, %1; cvt.u32.u64 %0, t; }"
        : "=r"(a) : "l"(p));
    return a;
}

#define CP_ASYNC16(smem, gptr) \
    asm volatile("cp.async.cg.shared.global [%0], [%1], 16;" \
                 :: "r"(smem), "l"(gptr) : "memory")
#define CP_ASYNC_COMMIT() asm volatile("cp.async.commit_group;" ::: "memory")
#define CP_ASYNC_WAIT(n)  asm volatile("cp.async.wait_group %0;" :: "n"(n) : "memory")

#define LDMATRIX_X4(r0,r1,r2,r3,addr) \
    asm volatile("ldmatrix.sync.aligned.m8n8.x4.shared.b16 {%0,%1,%2,%3}, [%4];" \
        : "=r"(r0),"=r"(r1),"=r"(r2),"=r"(r3) : "r"(addr))

__device__ __forceinline__ void mma_fp16(float* c, const uint32_t* a,
                                         const uint32_t* b) {
    asm volatile(
        "mma.sync.aligned.m16n8k16.row.col.f32.f16.f16.f32 "
        "{%0,%1,%2,%3}, {%4,%5,%6,%7}, {%8,%9}, {%0,%1,%2,%3};"
        : "+f"(c[0]), "+f"(c[1]), "+f"(c[2]), "+f"(c[3])
        : "r"(a[0]), "r"(a[1]), "r"(a[2]), "r"(a[3]), "r"(b[0]), "r"(b[1]));
}

// ---------------------------------------------------------------------------
// Fused layer-0 prep: x fp32 -> A0 fp16 AND P0[m,r] = x·D0[:,r,t].
// ---------------------------------------------------------------------------
__global__ __launch_bounds__(256)
void prep0_kernel(const float* __restrict__ x, const float* __restrict__ D,
                  __half* __restrict__ Ap, float* __restrict__ P)
{
    __shared__ float Ds[RNK][1024];
    const int tid  = threadIdx.x;
    const int wid  = tid >> 5;
    const int lane = tid & 31;
    const int row  = blockIdx.x * 8 + wid;
    const int t    = (blockIdx.x * 8) >> 10;

    for (int idx = tid; idx < 1024 * RNK; idx += 256) {
        int k = idx >> 3, r = idx & 7;
        Ds[r][k] = D[(size_t)k * 64 + r * 8 + t];
    }
    __syncthreads();

    const float4* xr = reinterpret_cast<const float4*>(x + (size_t)row * 1024);
    __half* arow = Ap + (size_t)row * 1024;
    float acc[RNK];
#pragma unroll
    for (int r = 0; r < RNK; ++r) acc[r] = 0.f;
#pragma unroll
    for (int i = 0; i < 8; ++i) {
        int kq = lane + 32 * i;
        float4 v = xr[kq];
        int k = kq << 2;
        union { __half h[4]; uint2 u; } hp;
        hp.h[0] = __float2half(v.x);
        hp.h[1] = __float2half(v.y);
        hp.h[2] = __float2half(v.z);
        hp.h[3] = __float2half(v.w);
        *reinterpret_cast<uint2*>(arow + k) = hp.u;
#pragma unroll
        for (int r = 0; r < RNK; ++r) {
            float4 d = *reinterpret_cast<const float4*>(&Ds[r][k]);
            acc[r] += v.x * d.x + v.y * d.y + v.z * d.z + v.w * d.w;
        }
    }
#pragma unroll
    for (int r = 0; r < RNK; ++r) {
        float v = acc[r];
#pragma unroll
        for (int o = 16; o > 0; o >>= 1) v += __shfl_down_sync(0xffffffffu, v, o);
        if (lane == 0) P[(size_t)row * RNK + r] = v;
    }
}

// ---------------------------------------------------------------------------
// P = sum over nb slabs of Pp (float4 over 16384 elements).
// ---------------------------------------------------------------------------
__global__ __launch_bounds__(256)
void reduceP_kernel(const float4* __restrict__ Pp, float4* __restrict__ P,
                    int nb)
{
    int i = blockIdx.x * 256 + threadIdx.x;      // over 16384
    float4 s = make_float4(0.f, 0.f, 0.f, 0.f);
    for (int b = 0; b < nb; ++b) {
        float4 v = Pp[(size_t)b * 16384 + i];
        s.x += v.x; s.y += v.y; s.z += v.z; s.w += v.w;
    }
    P[i] = s;
}

// ---------------------------------------------------------------------------
// One kernel converts all three W's: W[K,N] fp32 -> W^T[N,K] fp16.
// ---------------------------------------------------------------------------
__global__ __launch_bounds__(256)
void convertW3_kernel(const float* __restrict__ w0,
                      const float* __restrict__ w1,
                      const float* __restrict__ w2,
                      __half* __restrict__ Bbase)
{
    __shared__ float t[32][33];
    int b = blockIdx.x;
    const float* W; __half* Bp; int K, N, bx;
    if (b < 2048)      { W = w0; Bp = Bbase + W0_OFF; K = 1024; N = 2048; bx = b; }
    else if (b < 6144) { W = w1; Bp = Bbase + W1_OFF; K = 2048; N = 2048; bx = b - 2048; }
    else               { W = w2; Bp = Bbase + W2_OFF; K = 2048; N = 1024; bx = b - 6144; }
    const int nBlocksX = N / 32;
    const int n0 = (bx % nBlocksX) * 32;
    const int k0 = (bx / nBlocksX) * 32;

    int tx = threadIdx.x & 31, ty = threadIdx.x >> 5;   // 32 x 8
#pragma unroll
    for (int i = 0; i < 4; ++i)
        t[ty + 8 * i][tx] = W[(size_t)(k0 + ty + 8 * i) * N + n0 + tx];
    __syncthreads();
#pragma unroll
    for (int i = 0; i < 4; ++i) {
        int nn = ty + 8 * i;
        Bp[(size_t)(n0 + nn) * K + k0 + tx] = __float2half(t[tx][nn]);
    }
}

// ---------------------------------------------------------------------------
// Persistent fp16 mma.sync GEMM. Each CTA loops tiles (stride GRID_P); the
// cp.async ring prefetches the global (tile,chunk) sequence 2 ahead.
// mode==1: fp16 output + ReLU + P' partials to global slabs (Dn).
// mode==0: fp32 output, no ReLU, no partials.
// ---------------------------------------------------------------------------
__global__ __launch_bounds__(256, 2)
void gemm_mma_kernel(const __half* __restrict__ Ap,
                     const __half* __restrict__ Bp,
                     const float* __restrict__ bias,
                     const float* __restrict__ P,
                     const float* __restrict__ U,
                     void* __restrict__ Cp,
                     const float* __restrict__ Dn,
                     float* __restrict__ Pp,
                     int K, int N, int nTilesN, int nTiles, int mode)
{
    extern __shared__ char smem[];
    const uint32_t sbase = smem_u32(smem);
    const int tid  = threadIdx.x;
    const int wid  = tid >> 5;
    const int lane = tid & 31;
    const int nChunks = K / BK;

    const int warp_m = (wid >> 2) * 64;   // 0 / 64
    const int warp_n = (wid & 3) * 32;    // 0 / 32 / 64 / 96

    // ---- producer granule geometry (tile-independent) ----------------------
    int rG[4]; uint32_t qOff[4], sw[4];
#pragma unroll
    for (int i = 0; i < 4; ++i) {
        int g = tid + (i << 8);           // 16B granule id 0..1023
        rG[i]  = g >> 3;                  // row 0..127
        qOff[i] = (uint32_t)(g & 7) << 3; // element offset in row
        uint32_t off = (uint32_t)(rG[i] << 7) + ((g & 7) << 4);
        sw[i] = off ^ ((uint32_t)(rG[i] & 7) << 4);
    }

    // ---- ldmatrix addressing (tile-independent) ----------------------------
    uint32_t aRow[4], aXm[4];
    const uint32_t aCol = (uint32_t)(lane >> 4) << 4;
#pragma unroll
    for (int mi = 0; mi < 4; ++mi) {
        int r = warp_m + mi * 16 + (lane & 15);
        aRow[mi] = (uint32_t)r << 7;
        aXm[mi]  = (uint32_t)(r & 7) << 4;
    }
    uint32_t bRowP[2], bXmP[2];
    const uint32_t bCol = (uint32_t)((lane >> 3) & 1) << 4;
#pragma unroll
    for (int p = 0; p < 2; ++p) {
        int r = warp_n + (2 * p + ((lane >> 4) & 1)) * 8 + (lane & 7);
        bRowP[p] = (uint32_t)r << 7;
        bXmP[p]  = (uint32_t)(r & 7) << 4;
    }

    // ---- prefetch cursor ----------------------------------------------------
    int pf_tile = blockIdx.x, pf_c = 0;
    int pf_mB = 0, pf_nB = 0;
    bool pf_valid = (pf_tile < nTiles);
    if (pf_valid) {
        pf_mB = (pf_tile / nTilesN) * BM;
        pf_nB = (pf_tile % nTilesN) * BN;
    }
    int s_pf = 0, s_cons = 0;

    // issue one chunk's loads into stage s_pf, then advance cursor
    auto issue_and_advance = [&]() {
        if (pf_valid) {
            const uint32_t st = sbase + (uint32_t)s_pf * STAGE_BYTES;
            const uint32_t kc = (uint32_t)pf_c * BK;
#pragma unroll
            for (int i = 0; i < 4; ++i) {
                CP_ASYNC16(st + sw[i],
                           Ap + (size_t)(pf_mB + rG[i]) * (uint32_t)K + qOff[i] + kc);
                CP_ASYNC16(st + TILE_BYTES + sw[i],
                           Bp + (size_t)(pf_nB + rG[i]) * (uint32_t)K + qOff[i] + kc);
            }
        }
        CP_ASYNC_COMMIT();
        if (++s_pf == STAGES) s_pf = 0;
        if (pf_valid && ++pf_c == nChunks) {
            pf_c = 0;
            pf_tile += GRID_P;
            if (pf_tile < nTiles) {
                pf_mB = (pf_tile / nTilesN) * BM;
                pf_nB = (pf_tile % nTilesN) * BN;
            } else {
                pf_valid = false;
            }
        }
    };

    // ---- prologue: STAGES-1 groups in flight -------------------------------
#pragma unroll
    for (int i = 0; i < STAGES - 1; ++i) issue_and_advance();

    // epilogue smem region (beyond stages)
    float* bias_s = reinterpret_cast<float*>(smem + EPI_OFF);           // [128]
    float* Us     = reinterpret_cast<float*>(smem + EPI_OFF + 1024);    // [8][128]
    float* Ps     = reinterpret_cast<float*>(smem + EPI_OFF + 5120);    // [128][8]
    float* Dsn    = reinterpret_cast<float*>(smem + EPI_OFF + 9216);    // [128][8]

    // ---- persistent tile loop ----------------------------------------------
    for (int tile = blockIdx.x; tile < nTiles; tile += GRID_P) {
        const int mBase = (tile / nTilesN) * BM;
        const int nBase = (tile % nTilesN) * BN;
        const int task  = mBase >> 10;

        float acc[4][4][4];
#pragma unroll
        for (int mi = 0; mi < 4; ++mi)
#pragma unroll
            for (int ni = 0; ni < 4; ++ni)
#pragma unroll
                for (int j = 0; j < 4; ++j) acc[mi][ni][j] = 0.f;

        // ---- mainloop ------------------------------------------------------
        for (int c = 0; c < nChunks; ++c) {
            CP_ASYNC_WAIT(STAGES - 2);
            __syncthreads();

            issue_and_advance();

            const uint32_t stA = sbase + (uint32_t)s_cons * STAGE_BYTES;
            const uint32_t stB = stA + TILE_BYTES;

#pragma unroll
            for (int kk = 0; kk < 4; ++kk) {
                const uint32_t kb = (uint32_t)kk << 5;
                uint32_t a[4][4], b[4][2];
#pragma unroll
                for (int mi = 0; mi < 4; ++mi) {
                    uint32_t xo = (kb + aCol);
                    LDMATRIX_X4(a[mi][0], a[mi][1], a[mi][2], a[mi][3],
                                stA + aRow[mi] + (xo ^ aXm[mi]));
                }
#pragma unroll
                for (int p = 0; p < 2; ++p) {
                    uint32_t xo = (kb + bCol);
                    LDMATRIX_X4(b[2*p][0], b[2*p][1], b[2*p+1][0], b[2*p+1][1],
                                stB + bRowP[p] + (xo ^ bXmP[p]));
                }
#pragma unroll
                for (int mi = 0; mi < 4; ++mi)
#pragma unroll
                    for (int ni = 0; ni < 4; ++ni)
                        mma_fp16(acc[mi][ni], a[mi], b[ni]);
            }

            if (++s_cons == STAGES) s_cons = 0;
        }

        // ---- epilogue (stages keep prefetching the next tile) ---------------
        __syncthreads();   // all warps done with previous epilogue smem reads

        if (tid < BN) bias_s[tid] = bias[nBase + tid];
#pragma unroll
        for (int i = 0; i < 4; ++i) {
            int idx = tid + (i << 8);
            int r = idx >> 7, n = idx & 127;
            Us[idx] = U[((size_t)r * N + nBase + n) * T_TASKS + task];
        }
        {
            int row = tid >> 1, half = (tid & 1) << 2;
            float4 v = *reinterpret_cast<const float4*>(
                P + (size_t)(mBase + row) * RNK + half);
            *reinterpret_cast<float4*>(&Ps[row * RNK + half]) = v;
        }
        if (mode == 1) {
#pragma unroll
            for (int i = 0; i < 4; ++i) {
                int idx = tid + (i << 8);
                int n = idx >> 3, r = idx & 7;
                Dsn[idx] = Dn[(size_t)(nBase + n) * 64 + r * 8 + task];
            }
        }
        __syncthreads();

#pragma unroll
        for (int mi = 0; mi < 4; ++mi) {
#pragma unroll
            for (int half = 0; half < 2; ++half) {
                const int rloc = warp_m + mi * 16 + (lane >> 2) + half * 8;
                const int gm   = mBase + rloc;
                float pr[RNK];
                {
                    float4 p0 = *reinterpret_cast<const float4*>(&Ps[rloc * RNK]);
                    float4 p1 = *reinterpret_cast<const float4*>(&Ps[rloc * RNK + 4]);
                    pr[0]=p0.x; pr[1]=p0.y; pr[2]=p0.z; pr[3]=p0.w;
                    pr[4]=p1.x; pr[5]=p1.y; pr[6]=p1.z; pr[7]=p1.w;
                }
                float pp[RNK];
#pragma unroll
                for (int r = 0; r < RNK; ++r) pp[r] = 0.f;

#pragma unroll
                for (int ni = 0; ni < 4; ++ni) {
                    const int nloc = warp_n + ni * 8 + ((lane & 3) << 1);
                    float l0 = 0.f, l1 = 0.f;
#pragma unroll
                    for (int q = 0; q < RNK; ++q) {
                        l0 += pr[q] * Us[(q << 7) + nloc];
                        l1 += pr[q] * Us[(q << 7) + nloc + 1];
                    }
                    float v0 = acc[mi][ni][half * 2 + 0] + bias_s[nloc]     + 2.f * l0;
                    float v1 = acc[mi][ni][half * 2 + 1] + bias_s[nloc + 1] + 2.f * l1;
                    if (mode == 1) {
                        v0 = fmaxf(v0, 0.f); v1 = fmaxf(v1, 0.f);
                        __half2 hv;
                        hv.x = __float2half(v0);
                        hv.y = __float2half(v1);
                        __half* orow = (__half*)Cp + (size_t)gm * N + nBase + nloc;
                        *reinterpret_cast<__half2*>(orow) = hv;
#pragma unroll
                        for (int r = 0; r < RNK; ++r)
                            pp[r] += v0 * Dsn[(nloc << 3) + r]
                                   + v1 * Dsn[((nloc + 1) << 3) + r];
                    } else {
                        float* crow = (float*)Cp + (size_t)gm * N + nBase + nloc;
                        *reinterpret_cast<float2*>(crow) = make_float2(v0, v1);
                    }
                }

                if (mode == 1) {
                    // quad reduce (4 lanes share rloc), write slab directly
#pragma unroll
                    for (int r = 0; r < RNK; ++r) {
                        pp[r] += __shfl_xor_sync(0xffffffffu, pp[r], 1);
                        pp[r] += __shfl_xor_sync(0xffffffffu, pp[r], 2);
                    }
                    if ((lane & 3) == 0) {
                        const int slab = (nBase >> 7) * 4 + (wid & 3);
                        float* dst = Pp + (size_t)slab * (M_ROWS * RNK)
                                   + (size_t)gm * RNK;
                        *reinterpret_cast<float4*>(dst) =
                            make_float4(pp[0], pp[1], pp[2], pp[3]);
                        *reinterpret_cast<float4*>(dst + 4) =
                            make_float4(pp[4], pp[5], pp[6], pp[7]);
                    }
                }
            }
        }
    }
}

// ---------------------------------------------------------------------------
// Host launcher
// ---------------------------------------------------------------------------
extern "C" void kernel_launch(void* const* d_in, const int* in_sizes, int n_in,
                              void* d_out, int out_size)
{
    const float* x  = (const float*)d_in[0];
    const float* k0 = (const float*)d_in[1];
    const float* b0 = (const float*)d_in[2];
    const float* d0 = (const float*)d_in[3];
    const float* u0 = (const float*)d_in[4];
    const float* k1 = (const float*)d_in[5];
    const float* b1 = (const float*)d_in[6];
    const float* d1 = (const float*)d_in[7];
    const float* u1 = (const float*)d_in[8];
    const float* k2 = (const float*)d_in[9];
    const float* b2 = (const float*)d_in[10];
    const float* d2 = (const float*)d_in[11];
    const float* u2 = (const float*)d_in[12];
    float* out = (float*)d_out;

    __half *a0, *a1, *bS;
    float *p, *pp;
    cudaGetSymbolAddress((void**)&a0, g_A0);
    cudaGetSymbolAddress((void**)&a1, g_A1);
    cudaGetSymbolAddress((void**)&bS, g_B);
    cudaGetSymbolAddress((void**)&p,  g_p);
    cudaGetSymbolAddress((void**)&pp, g_pp);

    cudaFuncSetAttribute(gemm_mma_kernel,
                         cudaFuncAttributeMaxDynamicSharedMemorySize, SMEM_BYTES);

    // all weight conversions upfront (one node)
    convertW3_kernel<<<8192, 256>>>(k0, k1, k2, bS);

    // layer-0 prep: x -> A0 fp16 + P0, single pass over x
    prep0_kernel<<<M_ROWS / 8, 256>>>(x, d0, a0, p);

    // layer 0: A0[.,1024] -> A1[.,2048] fp16+ReLU, P' slabs (d1)
    gemm_mma_kernel<<<GRID_P, 256, SMEM_BYTES>>>(
        a0, bS + W0_OFF, b0, p, u0, a1, d1, pp,
        1024, 2048, 2048 / BN, (2048 / BN) * (M_ROWS / BM), 1);
    reduceP_kernel<<<64, 256>>>((const float4*)pp, (float4*)p, (2048 / BN) * 4);

    // layer 1: A1[.,2048] -> A0[.,2048] fp16+ReLU, P' slabs (d2)
    gemm_mma_kernel<<<GRID_P, 256, SMEM_BYTES>>>(
        a1, bS + W1_OFF, b1, p, u1, a0, d2, pp,
        2048, 2048, 2048 / BN, (2048 / BN) * (M_ROWS / BM), 1);
    reduceP_kernel<<<64, 256>>>((const float4*)pp, (float4*)p, (2048 / BN) * 4);

    // layer 2: A0[.,2048] -> out fp32 [.,1024], no ReLU
    gemm_mma_kernel<<<GRID_P, 256, SMEM_BYTES>>>(
        a0, bS + W2_OFF, b2, p, u2, out, nullptr, pp,
        2048, 1024, 1024 / BN, (1024 / BN) * (M_ROWS / BM), 0);
}